// round 12
// baseline (speedup 1.0000x reference)
#include <cuda_runtime.h>
#include <math.h>

// ---------------------------------------------------------------------------
// Problem constants
// ---------------------------------------------------------------------------
#define NCH   8192
#define LLEN  128
#define DDIM  256
#define KSEL  8
#define NHEAD 4
#define DHEAD 64
#define FFDIM 1024
#define NROWS (NCH * KSEL)          // 65536 tokens
#define NEGMAX (-3.402823466e38f)   // float32 finfo.min (reference's `neg`)

// ---------------------------------------------------------------------------
// Scratch (static __device__ arrays: allocation-free, graph-safe)
// ---------------------------------------------------------------------------
__device__ float g_X   [NROWS * DDIM];     // residual stream x
__device__ float g_LN  [NROWS * DDIM];     // layernorm output (GEMM A)
__device__ float g_QKV [NROWS * 3 * DDIM]; // qkv projections
__device__ float g_ATT [NROWS * DDIM];     // attention output (pre w_o)
__device__ float g_FF  [NROWS * FFDIM];    // FF1 activation
__device__ unsigned char g_picked[NROWS];  // per-slot valid flag
__device__ float g_pooled[NCH * DDIM];     // pooled features
__device__ float g_lc  [NCH];              // log1p(count)
__device__ float g_head[NCH * FFDIM];      // head hidden
__device__ float g_w1p [FFDIM * DDIM];     // w_out1[:, :256] repacked (ldb=256)
__device__ float g_w1c [FFDIM];            // w_out1[:, 256]

// ---------------------------------------------------------------------------
// f32x2 packed-FMA helpers (sm_103a: fp32 FFMA is half-rate; f32x2 restores it)
// ---------------------------------------------------------------------------
__device__ __forceinline__ unsigned long long pack2(float lo, float hi) {
    unsigned long long r;
    asm("mov.b64 %0, {%1, %2};" : "=l"(r) : "f"(lo), "f"(hi));
    return r;
}
__device__ __forceinline__ void unpack2(unsigned long long v, float& lo, float& hi) {
    asm("mov.b64 {%0, %1}, %2;" : "=f"(lo), "=f"(hi) : "l"(v));
}
__device__ __forceinline__ void ffma2(unsigned long long& d, unsigned long long a,
                                      unsigned long long b) {
    asm("fma.rn.f32x2 %0, %1, %2, %0;" : "+l"(d) : "l"(a), "l"(b));
}

__device__ __forceinline__ float gelu_exact(float x) {
    return 0.5f * x * (1.0f + erff(x * 0.70710678118654752f));
}

// ---------------------------------------------------------------------------
// Kernel 1: top-K selection + gather + pos_embed add
// One block per chain, 256 threads.
// ---------------------------------------------------------------------------
__global__ void select_gather_kernel(const float* __restrict__ v,
                                     const int* __restrict__ batch_idx,
                                     const void* __restrict__ mask_raw,
                                     const float* __restrict__ rank_scores,
                                     const float* __restrict__ pos_embed)
{
    const int c = blockIdx.x;
    const int tid = threadIdx.x;

    __shared__ unsigned long long keys[LLEN];
    __shared__ unsigned long long red[8];
    __shared__ int sel[KSEL];
    __shared__ int s_mode;

    // --- runtime mask dtype detection (int32 {0,1} / float32 {0,1} / byte) ---
    if (tid == 0) {
        const unsigned int* w = (const unsigned int*)mask_raw;
        bool all01 = true, allf = true;
        for (int i = 0; i < 64; i++) {
            unsigned int x = w[i];
            if (x > 1u) all01 = false;
            if (x != 0u && x != 0x3F800000u) allf = false;
        }
        s_mode = all01 ? 0 : (allf ? 1 : 2);
    }
    __syncthreads();
    const int mode = s_mode;

    if (tid < LLEN) {
        bool m;
        if (mode == 0)      m = ((const int*)mask_raw)[c * LLEN + tid] != 0;
        else if (mode == 1) m = ((const float*)mask_raw)[c * LLEN + tid] != 0.0f;
        else                m = ((const unsigned char*)mask_raw)[c * LLEN + tid] != 0;
        unsigned long long key = 0ULL;
        if (m) {
            float sc = rank_scores[c * LLEN + tid];
            unsigned int ub = __float_as_uint(sc);
            ub = (ub & 0x80000000u) ? ~ub : (ub | 0x80000000u);  // order-preserving map
            // low bits: (127 - idx) so that equal scores break ties toward lower index
            key = ((unsigned long long)ub << 32) | (unsigned int)(LLEN - 1 - tid);
        }
        keys[tid] = key;
    }
    __syncthreads();

    // 8 rounds of argmax over 128 keys (warp shuffle + cross-warp reduce)
    for (int r = 0; r < KSEL; r++) {
        unsigned long long kk = (tid < LLEN) ? keys[tid] : 0ULL;
        #pragma unroll
        for (int o = 16; o; o >>= 1) {
            unsigned long long other = __shfl_xor_sync(0xffffffffu, kk, o);
            if (other > kk) kk = other;
        }
        if ((tid & 31) == 0) red[tid >> 5] = kk;
        __syncthreads();
        if (tid == 0) {
            unsigned long long best = red[0];
            for (int w2 = 1; w2 < 4; w2++) if (red[w2] > best) best = red[w2];
            if (best == 0ULL) {
                sel[r] = -1;                       // fewer than K masked positions
            } else {
                int idx = (LLEN - 1) - (int)(best & 0xffffffffULL);
                sel[r] = idx;
                keys[idx] = 0ULL;
            }
        }
        __syncthreads();
    }

    // sort selected indices ascending (pads at the end), like reference
    if (tid == 0) {
        int tmp[KSEL]; int np = 0;
        for (int r = 0; r < KSEL; r++) if (sel[r] >= 0) tmp[np++] = sel[r];
        for (int i = 1; i < np; i++) {
            int x = tmp[i]; int j = i - 1;
            while (j >= 0 && tmp[j] > x) { tmp[j + 1] = tmp[j]; j--; }
            tmp[j + 1] = x;
        }
        for (int r = 0; r < np; r++)   sel[r] = tmp[r];
        for (int r = np; r < KSEL; r++) sel[r] = -1;
    }
    __syncthreads();

    // gather v rows + pos_embed (tid = feature dim)
    #pragma unroll
    for (int k = 0; k < KSEL; k++) {
        int idx = sel[k];
        float val = 0.0f;
        if (idx >= 0) {
            int mi = batch_idx[c * LLEN + idx];
            val = v[(size_t)mi * DDIM + tid];
        }
        g_X[((size_t)c * KSEL + k) * DDIM + tid] = val + pos_embed[k * DDIM + tid];
        if (tid == 0) g_picked[c * KSEL + k] = (idx >= 0) ? 1 : 0;
    }
}

// ---------------------------------------------------------------------------
// Kernel 2: LayerNorm (one warp per 256-wide row, 8 rows/block)
// ---------------------------------------------------------------------------
__global__ void ln_kernel(const float* __restrict__ src, float* __restrict__ dst,
                          const float* __restrict__ gw, const float* __restrict__ bw)
{
    const int gtid = blockIdx.x * blockDim.x + threadIdx.x;
    const int row = gtid >> 5;
    const int lane = threadIdx.x & 31;
    const float* x = src + (size_t)row * DDIM + lane * 8;
    float4 v0 = *(const float4*)(x);
    float4 v1 = *(const float4*)(x + 4);

    float s = v0.x + v0.y + v0.z + v0.w + v1.x + v1.y + v1.z + v1.w;
    float q = v0.x * v0.x + v0.y * v0.y + v0.z * v0.z + v0.w * v0.w
            + v1.x * v1.x + v1.y * v1.y + v1.z * v1.z + v1.w * v1.w;
    #pragma unroll
    for (int o = 16; o; o >>= 1) {
        s += __shfl_xor_sync(0xffffffffu, s, o);
        q += __shfl_xor_sync(0xffffffffu, q, o);
    }
    const float mean = s * (1.0f / 256.0f);
    const float var  = q * (1.0f / 256.0f) - mean * mean;
    const float rs   = rsqrtf(var + 1e-5f);

    const int d = lane * 8;
    float4 gg0 = *(const float4*)(gw + d);
    float4 gg1 = *(const float4*)(gw + d + 4);
    float4 bb0 = *(const float4*)(bw + d);
    float4 bb1 = *(const float4*)(bw + d + 4);
    float4 o0, o1;
    o0.x = (v0.x - mean) * rs * gg0.x + bb0.x;
    o0.y = (v0.y - mean) * rs * gg0.y + bb0.y;
    o0.z = (v0.z - mean) * rs * gg0.z + bb0.z;
    o0.w = (v0.w - mean) * rs * gg0.w + bb0.w;
    o1.x = (v1.x - mean) * rs * gg1.x + bb1.x;
    o1.y = (v1.y - mean) * rs * gg1.y + bb1.y;
    o1.z = (v1.z - mean) * rs * gg1.z + bb1.z;
    o1.w = (v1.w - mean) * rs * gg1.w + bb1.w;
    float* dp = dst + (size_t)row * DDIM + d;
    *(float4*)(dp)     = o0;
    *(float4*)(dp + 4) = o1;
}

// ---------------------------------------------------------------------------
// Kernel 3: generic NT GEMM with fused epilogues
// C[M,N] = A[M,K] * B[N,K]^T (+ bias / residual / gelu / head feature)
// 128x128x16 tiles, 256 threads, 8x8 micro-tile, f32x2 packed FMA.
// Requires M%128==0, N%128==0, K%16==0, lda/ldb/ldc multiples of 4.
// ---------------------------------------------------------------------------
#define GBM 128
#define GBN 128
#define GBK 16

// EPI: 0 = bias, 1 = bias+residual, 2 = gelu(bias), 3 = gelu(bias + lc[m]*wc[n])
template <int EPI>
__global__ __launch_bounds__(256, 2)
void gemm_nt(const float* __restrict__ A, int lda,
             const float* __restrict__ B, int ldb,
             const float* __restrict__ bias,
             const float* __restrict__ res,   // residual (EPI=1) or wcol (EPI=3)
             const float* __restrict__ lcv,   // per-row scalar (EPI=3)
             float* __restrict__ C, int ldc, int K)
{
    __shared__ float As[GBK][GBM + 4];
    __shared__ float Bs[GBK][GBN + 4];

    const int bm = blockIdx.y * GBM;
    const int bn = blockIdx.x * GBN;
    const int tid = threadIdx.x;
    const int tx = tid & 15;          // N direction
    const int ty = tid >> 4;          // M direction
    const int lm = tid >> 2;          // loader row (0..63)
    const int lk = (tid & 3) << 2;    // loader k   (0,4,8,12)

    unsigned long long acc[8][4];     // acc[j][i2]: cols tx*8+j, rows ty*8+2*i2{+1}
    #pragma unroll
    for (int j = 0; j < 8; j++)
        #pragma unroll
        for (int i = 0; i < 4; i++) acc[j][i] = 0ULL;

    const float* Ap = A + (size_t)(bm + lm) * lda + lk;
    const float* Bp = B + (size_t)(bn + lm) * ldb + lk;

    for (int k0 = 0; k0 < K; k0 += GBK) {
        float4 a0 = *(const float4*)(Ap + k0);
        float4 a1 = *(const float4*)(Ap + k0 + (size_t)64 * lda);
        float4 b0 = *(const float4*)(Bp + k0);
        float4 b1 = *(const float4*)(Bp + k0 + (size_t)64 * ldb);
        As[lk + 0][lm] = a0.x; As[lk + 1][lm] = a0.y;
        As[lk + 2][lm] = a0.z; As[lk + 3][lm] = a0.w;
        As[lk + 0][lm + 64] = a1.x; As[lk + 1][lm + 64] = a1.y;
        As[lk + 2][lm + 64] = a1.z; As[lk + 3][lm + 64] = a1.w;
        Bs[lk + 0][lm] = b0.x; Bs[lk + 1][lm] = b0.y;
        Bs[lk + 2][lm] = b0.z; Bs[lk + 3][lm] = b0.w;
        Bs[lk + 0][lm + 64] = b1.x; Bs[lk + 1][lm + 64] = b1.y;
        Bs[lk + 2][lm + 64] = b1.z; Bs[lk + 3][lm + 64] = b1.w;
        __syncthreads();

        #pragma unroll
        for (int kk = 0; kk < GBK; kk++) {
            const float4 av0 = *(const float4*)&As[kk][ty * 8];
            const float4 av1 = *(const float4*)&As[kk][ty * 8 + 4];
            const float4 bv0 = *(const float4*)&Bs[kk][tx * 8];
            const float4 bv1 = *(const float4*)&Bs[kk][tx * 8 + 4];
            unsigned long long a01 = pack2(av0.x, av0.y);
            unsigned long long a23 = pack2(av0.z, av0.w);
            unsigned long long a45 = pack2(av1.x, av1.y);
            unsigned long long a67 = pack2(av1.z, av1.w);
            float bv[8] = {bv0.x, bv0.y, bv0.z, bv0.w, bv1.x, bv1.y, bv1.z, bv1.w};
            #pragma unroll
            for (int j = 0; j < 8; j++) {
                unsigned long long bb = pack2(bv[j], bv[j]);
                ffma2(acc[j][0], a01, bb);
                ffma2(acc[j][1], a23, bb);
                ffma2(acc[j][2], a45, bb);
                ffma2(acc[j][3], a67, bb);
            }
        }
        __syncthreads();
    }

    // epilogue
    #pragma unroll
    for (int i2 = 0; i2 < 4; i2++) {
        #pragma unroll
        for (int p = 0; p < 2; p++) {
            const int r = bm + ty * 8 + i2 * 2 + p;
            float lc = 0.0f;
            if (EPI == 3) lc = lcv[r];
            float vals[8];
            #pragma unroll
            for (int j = 0; j < 8; j++) {
                float lo, hi;
                unpack2(acc[j][i2], lo, hi);
                vals[j] = p ? hi : lo;
            }
            #pragma unroll
            for (int j4 = 0; j4 < 8; j4 += 4) {
                float4 o;
                float* op = &o.x;
                #pragma unroll
                for (int u = 0; u < 4; u++) {
                    const int col = bn + tx * 8 + j4 + u;
                    float val = vals[j4 + u] + bias[col];
                    if (EPI == 1) val += res[(size_t)r * ldc + col];
                    if (EPI == 2) val = gelu_exact(val);
                    if (EPI == 3) val = gelu_exact(val + lc * res[col]);
                    op[u] = val;
                }
                *(float4*)(C + (size_t)r * ldc + bn + tx * 8 + j4) = o;
            }
        }
    }
}

// ---------------------------------------------------------------------------
// Kernel 4: attention (seqlen 8, 4 heads x 64). One block (256 thr) per chain.
// ---------------------------------------------------------------------------
__global__ void attn_kernel()
{
    __shared__ float Qs[KSEL][260];
    __shared__ float Ks[KSEL][260];
    __shared__ float Vs[KSEL][260];
    __shared__ float att[NHEAD][KSEL][KSEL];
    __shared__ unsigned char pk[KSEL];

    const int c = blockIdx.x;
    const int tid = threadIdx.x;
    const float* base = g_QKV + (size_t)c * KSEL * (3 * DDIM);

    #pragma unroll
    for (int it = 0; it < 6; it++) {
        int i = tid + it * 256;            // float4 index over 8*768/4 = 1536
        int tok = i / 192;
        int off = (i % 192) * 4;
        float4 val = *(const float4*)(base + (size_t)tok * 768 + off);
        float* dst;
        if (off < 256)      dst = &Qs[tok][off];
        else if (off < 512) dst = &Ks[tok][off - 256];
        else                dst = &Vs[tok][off - 512];
        *(float4*)dst = val;
    }
    if (tid < KSEL) pk[tid] = g_picked[c * KSEL + tid];
    __syncthreads();

    bool anyp = false;
    #pragma unroll
    for (int j2 = 0; j2 < KSEL; j2++) anyp |= (pk[j2] != 0);

    const int h = tid >> 6;
    const int q = (tid >> 3) & 7;
    const int j = tid & 7;
    const float* qp = &Qs[q][h * DHEAD];
    const float* kp = &Ks[j][h * DHEAD];
    float s = 0.0f;
    #pragma unroll
    for (int d = 0; d < DHEAD; d++) s = fmaf(qp[d], kp[d], s);
    s *= 0.125f;  // 1/sqrt(64)

    const bool valid = (pk[j] != 0) || (j == 0 && !anyp);  // reference's empty fix
    if (!valid) s = NEGMAX;

    float mx = s;
    #pragma unroll
    for (int o = 4; o; o >>= 1) mx = fmaxf(mx, __shfl_xor_sync(0xffffffffu, mx, o));
    float e = valid ? expf(s - mx) : 0.0f;
    float sum = e;
    #pragma unroll
    for (int o = 4; o; o >>= 1) sum += __shfl_xor_sync(0xffffffffu, sum, o);
    att[h][q][j] = e / sum;
    __syncthreads();

    float* outp = g_ATT + (size_t)c * KSEL * DDIM;
    const int dim = tid;
    const int hh = dim >> 6;
    #pragma unroll
    for (int q2 = 0; q2 < KSEL; q2++) {
        float o2 = 0.0f;
        #pragma unroll
        for (int j2 = 0; j2 < KSEL; j2++) o2 = fmaf(att[hh][q2][j2], Vs[j2][dim], o2);
        outp[(size_t)q2 * DDIM + dim] = o2;
    }
}

// ---------------------------------------------------------------------------
// Kernel 5: masked mean pool + log1p(count)
// ---------------------------------------------------------------------------
__global__ void pool_kernel(const float* __restrict__ count)
{
    const int c = blockIdx.x;
    const int d = threadIdx.x;
    float s = 0.0f;
    int np = 0;
    #pragma unroll
    for (int k = 0; k < KSEL; k++) {
        if (g_picked[c * KSEL + k]) {
            s += g_X[((size_t)c * KSEL + k) * DDIM + d];
            np++;
        }
    }
    g_pooled[(size_t)c * DDIM + d] = (np > 0) ? (s / (float)np) : 0.0f;
    if (d == 0) g_lc[c] = log1pf(count[c]);
}

// ---------------------------------------------------------------------------
// Kernel 6: repack w_out1 [1024,257] into [1024,256] + column-256 vector
// ---------------------------------------------------------------------------
__global__ void repack_w1_kernel(const float* __restrict__ w1)
{
    int i = blockIdx.x * 256 + threadIdx.x;
    if (i < FFDIM * (DDIM + 1)) {
        int n = i / (DDIM + 1);
        int k = i % (DDIM + 1);
        float val = w1[i];
        if (k < DDIM) g_w1p[n * DDIM + k] = val;
        else          g_w1c[n] = val;
    }
}

// ---------------------------------------------------------------------------
// Launch
// ---------------------------------------------------------------------------
extern "C" void kernel_launch(void* const* d_in, const int* in_sizes, int n_in,
                              void* d_out, int out_size)
{
    (void)in_sizes; (void)n_in; (void)out_size;
    const float* v           = (const float*)d_in[0];
    const int*   batch_idx   = (const int*)  d_in[1];
    const void*  mask        =               d_in[2];
    const float* count       = (const float*)d_in[3];
    const float* rank_scores = (const float*)d_in[4];
    const float* pos_embed   = (const float*)d_in[5];
    const float* w_qkv       = (const float*)d_in[6];
    const float* b_qkv       = (const float*)d_in[7];
    const float* w_o         = (const float*)d_in[8];
    const float* b_o         = (const float*)d_in[9];
    const float* ln1_g       = (const float*)d_in[10];
    const float* ln1_b       = (const float*)d_in[11];
    const float* ln2_g       = (const float*)d_in[12];
    const float* ln2_b       = (const float*)d_in[13];
    const float* w_ff1       = (const float*)d_in[14];
    const float* b_ff1       = (const float*)d_in[15];
    const float* w_ff2       = (const float*)d_in[16];
    const float* b_ff2       = (const float*)d_in[17];
    const float* w_out1      = (const float*)d_in[18];
    const float* b_out1      = (const float*)d_in[19];
    const float* w_out2      = (const float*)d_in[20];
    const float* b_out2      = (const float*)d_in[21];
    float* out = (float*)d_out;

    float *X, *LN, *QKV, *ATT, *FF, *POOL, *LC, *HEAD, *W1P, *W1C;
    cudaGetSymbolAddress((void**)&X,    g_X);
    cudaGetSymbolAddress((void**)&LN,   g_LN);
    cudaGetSymbolAddress((void**)&QKV,  g_QKV);
    cudaGetSymbolAddress((void**)&ATT,  g_ATT);
    cudaGetSymbolAddress((void**)&FF,   g_FF);
    cudaGetSymbolAddress((void**)&POOL, g_pooled);
    cudaGetSymbolAddress((void**)&LC,   g_lc);
    cudaGetSymbolAddress((void**)&HEAD, g_head);
    cudaGetSymbolAddress((void**)&W1P,  g_w1p);
    cudaGetSymbolAddress((void**)&W1C,  g_w1c);

    // 1. selection + gather (+ pos_embed)
    select_gather_kernel<<<NCH, 256>>>(v, batch_idx, mask, rank_scores, pos_embed);

    // 2. LN1
    ln_kernel<<<NROWS * 32 / 256, 256>>>(X, LN, ln1_g, ln1_b);

    // 3. QKV = LN @ w_qkv^T + b_qkv        [65536 x 768]
    gemm_nt<0><<<dim3(3 * DDIM / GBN, NROWS / GBM), 256>>>(
        LN, DDIM, w_qkv, DDIM, b_qkv, nullptr, nullptr, QKV, 3 * DDIM, DDIM);

    // 4. attention
    attn_kernel<<<NCH, 256>>>();

    // 5. X = X + ATT @ w_o^T + b_o
    gemm_nt<1><<<dim3(DDIM / GBN, NROWS / GBM), 256>>>(
        ATT, DDIM, w_o, DDIM, b_o, X, nullptr, X, DDIM, DDIM);

    // 6. LN2
    ln_kernel<<<NROWS * 32 / 256, 256>>>(X, LN, ln2_g, ln2_b);

    // 7. FF = gelu(LN @ w_ff1^T + b_ff1)   [65536 x 1024]
    gemm_nt<2><<<dim3(FFDIM / GBN, NROWS / GBM), 256>>>(
        LN, DDIM, w_ff1, DDIM, b_ff1, nullptr, nullptr, FF, FFDIM, DDIM);

    // 8. X = X + FF @ w_ff2^T + b_ff2
    gemm_nt<1><<<dim3(DDIM / GBN, NROWS / GBM), 256>>>(
        FF, FFDIM, w_ff2, FFDIM, b_ff2, X, nullptr, X, DDIM, FFDIM);

    // 9. masked mean pool + log1p(count)
    pool_kernel<<<NCH, 256>>>(count);

    // 10. repack w_out1 for aligned loads
    repack_w1_kernel<<<(FFDIM * (DDIM + 1) + 255) / 256, 256>>>(w_out1);

    // 11. HEAD = gelu(pooled @ w1p^T + lc*w1c + b_out1)   [8192 x 1024]
    gemm_nt<3><<<dim3(FFDIM / GBN, NCH / GBM), 256>>>(
        POOL, DDIM, W1P, DDIM, b_out1, W1C, LC, HEAD, FFDIM, DDIM);

    // 12. out = HEAD @ w_out2^T + b_out2   [8192 x 256]
    gemm_nt<0><<<dim3(DDIM / GBN, NCH / GBM), 256>>>(
        HEAD, FFDIM, w_out2, FFDIM, b_out2, nullptr, nullptr, out, DDIM, FFDIM);
}